// round 11
// baseline (speedup 1.0000x reference)
#include <cuda_runtime.h>

// TokenMixer: out = x_pos * (1 - sigmoid( <x_pre,x_pos> / (||x_pre||*||x_pos||) ))
// Shapes: [N=4096, B=16, C=512] f32. One warp per row.
//
// FINAL (== R7, session best): 256-bit v8 global ld/st, one warp per row,
// x_pos kept in registers (read exactly once), 3-scalar warp tree reduce,
// MUFU.RSQ tail (1/max(sqrt(s),eps) == min(rsqrt(s),1e12)),
// 1-sigmoid(d) == 1/(1+exp(d)).
//
// Converged roofline, reproduced across 5 runs: 52.7 +/- 0.1 us kernel,
// 6.63-6.68 TB/s (84% of 8TB/s HBM spec). Plateau invariant to occupancy
// (49-82%), per-warp MLP (8-16 loads), L1 bypass (.cg), minBlocks hints;
// L2 evict-first (.cs) and cross-row prefetch/persistence both regress.
// This is the DRAM controller's effective rate for a 2:1 read:write
// interleaved stream of 384 MB mandatory traffic — no software lever left.

#define ROWS_TOTAL (4096 * 16)
#define FLOATS_PER_ROW 512
#define WARPS_PER_BLOCK 8

__device__ __forceinline__ void ldg256(const float* __restrict__ p, float r[8]) {
    asm("ld.global.v8.f32 {%0,%1,%2,%3,%4,%5,%6,%7}, [%8];"
        : "=f"(r[0]), "=f"(r[1]), "=f"(r[2]), "=f"(r[3]),
          "=f"(r[4]), "=f"(r[5]), "=f"(r[6]), "=f"(r[7])
        : "l"(p));
}

__device__ __forceinline__ void stg256(float* __restrict__ p, const float r[8]) {
    asm volatile("st.global.v8.f32 [%0], {%1,%2,%3,%4,%5,%6,%7,%8};"
        :: "l"(p),
           "f"(r[0]), "f"(r[1]), "f"(r[2]), "f"(r[3]),
           "f"(r[4]), "f"(r[5]), "f"(r[6]), "f"(r[7])
        : "memory");
}

__global__ __launch_bounds__(WARPS_PER_BLOCK * 32)
void token_mixer_kernel(const float* __restrict__ pre,
                        const float* __restrict__ pos,
                        float* __restrict__ out) {
    const int warp_id = threadIdx.x >> 5;
    const int lane    = threadIdx.x & 31;
    const int row     = blockIdx.x * WARPS_PER_BLOCK + warp_id;  // exact: 8192*8 == ROWS_TOTAL

    const size_t base = (size_t)row * FLOATS_PER_ROW + lane * 8;
    const float* __restrict__ p = pre + base;
    const float* __restrict__ q = pos + base;

    // Front-batch: 4 x 256-bit loads (2 per input). Warp covers 1KB per op.
    float a0[8], a1[8], b0[8], b1[8];
    ldg256(p,       a0);
    ldg256(q,       b0);
    ldg256(p + 256, a1);
    ldg256(q + 256, b1);

    float dot = 0.f, sa = 0.f, sb = 0.f;
    #pragma unroll
    for (int i = 0; i < 8; i++) {
        dot += a0[i] * b0[i];
        sa  += a0[i] * a0[i];
        sb  += b0[i] * b0[i];
        dot += a1[i] * b1[i];
        sa  += a1[i] * a1[i];
        sb  += b1[i] * b1[i];
    }

    // Warp tree-reduce the three scalars (interleaved chains).
    #pragma unroll
    for (int off = 16; off > 0; off >>= 1) {
        dot += __shfl_xor_sync(0xffffffffu, dot, off);
        sa  += __shfl_xor_sync(0xffffffffu, sa,  off);
        sb  += __shfl_xor_sync(0xffffffffu, sb,  off);
    }

    // 1/max(sqrt(s), 1e-12) == min(rsqrt(s), 1e12): two MUFU.RSQ, no div.
    const float ra = fminf(rsqrtf(sa), 1e12f);
    const float rb = fminf(rsqrtf(sb), 1e12f);
    const float d  = dot * ra * rb;
    // 1 - sigmoid(d) = 1 / (1 + exp(d))
    const float w  = 1.0f / (1.0f + __expf(d));

    #pragma unroll
    for (int i = 0; i < 8; i++) { b0[i] *= w; b1[i] *= w; }

    float* __restrict__ o = out + base;
    stg256(o,       b0);
    stg256(o + 256, b1);
}

extern "C" void kernel_launch(void* const* d_in, const int* in_sizes, int n_in,
                              void* d_out, int out_size) {
    const float* pre = (const float*)d_in[0];
    const float* pos = (const float*)d_in[1];
    float* out = (float*)d_out;
    const int blocks = ROWS_TOTAL / WARPS_PER_BLOCK;  // 8192
    token_mixer_kernel<<<blocks, WARPS_PER_BLOCK * 32>>>(pre, pos, out);
}

// round 12
// speedup vs baseline: 1.0041x; 1.0041x over previous
#include <cuda_runtime.h>

// TokenMixer: out = x_pos * (1 - sigmoid( <x_pre,x_pos> / (||x_pre||*||x_pos||) ))
// Shapes: [N=4096, B=16, C=512] f32. One warp per row.
//
// R12 (final structure == R7, block 256 -> 512): identical per-warp code;
// 16 warps/block halves block count (8192 -> 4096) -> fewer wave-transition
// events. 256-bit v8 global ld/st, x_pos kept in registers (read once),
// 3-scalar warp tree reduce, MUFU.RSQ tail, 1-sigmoid(d) == 1/(1+exp(d)).
//
// Converged roofline across 6 runs: 52.7-53.3us kernel, 6.58-6.68 TB/s
// (83-84% of HBM spec). Invariant to occupancy, MLP/warp, L1/L2 policy,
// prefetch, minBlocks. DRAM-controller-limited; no software lever remains.

#define ROWS_TOTAL (4096 * 16)
#define FLOATS_PER_ROW 512
#define WARPS_PER_BLOCK 16

__device__ __forceinline__ void ldg256(const float* __restrict__ p, float r[8]) {
    asm("ld.global.v8.f32 {%0,%1,%2,%3,%4,%5,%6,%7}, [%8];"
        : "=f"(r[0]), "=f"(r[1]), "=f"(r[2]), "=f"(r[3]),
          "=f"(r[4]), "=f"(r[5]), "=f"(r[6]), "=f"(r[7])
        : "l"(p));
}

__device__ __forceinline__ void stg256(float* __restrict__ p, const float r[8]) {
    asm volatile("st.global.v8.f32 [%0], {%1,%2,%3,%4,%5,%6,%7,%8};"
        :: "l"(p),
           "f"(r[0]), "f"(r[1]), "f"(r[2]), "f"(r[3]),
           "f"(r[4]), "f"(r[5]), "f"(r[6]), "f"(r[7])
        : "memory");
}

__global__ __launch_bounds__(WARPS_PER_BLOCK * 32)
void token_mixer_kernel(const float* __restrict__ pre,
                        const float* __restrict__ pos,
                        float* __restrict__ out) {
    const int warp_id = threadIdx.x >> 5;
    const int lane    = threadIdx.x & 31;
    const int row     = blockIdx.x * WARPS_PER_BLOCK + warp_id;  // exact: 4096*16 == ROWS_TOTAL

    const size_t base = (size_t)row * FLOATS_PER_ROW + lane * 8;
    const float* __restrict__ p = pre + base;
    const float* __restrict__ q = pos + base;

    // Front-batch: 4 x 256-bit loads (2 per input). Warp covers 1KB per op.
    float a0[8], a1[8], b0[8], b1[8];
    ldg256(p,       a0);
    ldg256(q,       b0);
    ldg256(p + 256, a1);
    ldg256(q + 256, b1);

    float dot = 0.f, sa = 0.f, sb = 0.f;
    #pragma unroll
    for (int i = 0; i < 8; i++) {
        dot += a0[i] * b0[i];
        sa  += a0[i] * a0[i];
        sb  += b0[i] * b0[i];
        dot += a1[i] * b1[i];
        sa  += a1[i] * a1[i];
        sb  += b1[i] * b1[i];
    }

    // Warp tree-reduce the three scalars (interleaved chains).
    #pragma unroll
    for (int off = 16; off > 0; off >>= 1) {
        dot += __shfl_xor_sync(0xffffffffu, dot, off);
        sa  += __shfl_xor_sync(0xffffffffu, sa,  off);
        sb  += __shfl_xor_sync(0xffffffffu, sb,  off);
    }

    // 1/max(sqrt(s), 1e-12) == min(rsqrt(s), 1e12): two MUFU.RSQ, no div.
    const float ra = fminf(rsqrtf(sa), 1e12f);
    const float rb = fminf(rsqrtf(sb), 1e12f);
    const float d  = dot * ra * rb;
    // 1 - sigmoid(d) = 1 / (1 + exp(d))
    const float w  = 1.0f / (1.0f + __expf(d));

    #pragma unroll
    for (int i = 0; i < 8; i++) { b0[i] *= w; b1[i] *= w; }

    float* __restrict__ o = out + base;
    stg256(o,       b0);
    stg256(o + 256, b1);
}

extern "C" void kernel_launch(void* const* d_in, const int* in_sizes, int n_in,
                              void* d_out, int out_size) {
    const float* pre = (const float*)d_in[0];
    const float* pos = (const float*)d_in[1];
    float* out = (float*)d_out;
    const int blocks = ROWS_TOTAL / WARPS_PER_BLOCK;  // 4096
    token_mixer_kernel<<<blocks, WARPS_PER_BLOCK * 32>>>(pre, pos, out);
}

// round 13
// speedup vs baseline: 1.0109x; 1.0068x over previous
#include <cuda_runtime.h>

// TokenMixer: out = x_pos * (1 - sigmoid( <x_pre,x_pos> / (||x_pre||*||x_pos||) ))
// Shapes: [N=4096, B=16, C=512] f32. One warp per row.
//
// R13 (= R12 structure, block 512 -> 1024): CTA-granularity probe. R12's
// 256->512 move bought +1.3% DRAM (51.7us, 6778 GB/s) — fewer block
// boundary events. One more halving: 32 warps/block, 2048 blocks; one CTA
// fills an SM (40 regs * 1024 thr = 40K RF). Per-warp code unchanged:
// 256-bit v8 ld/st, x_pos register-resident (read once), 3-scalar warp
// reduce, MUFU.RSQ tail, 1-sigmoid(d) == 1/(1+exp(d)).

#define ROWS_TOTAL (4096 * 16)
#define FLOATS_PER_ROW 512
#define WARPS_PER_BLOCK 32

__device__ __forceinline__ void ldg256(const float* __restrict__ p, float r[8]) {
    asm("ld.global.v8.f32 {%0,%1,%2,%3,%4,%5,%6,%7}, [%8];"
        : "=f"(r[0]), "=f"(r[1]), "=f"(r[2]), "=f"(r[3]),
          "=f"(r[4]), "=f"(r[5]), "=f"(r[6]), "=f"(r[7])
        : "l"(p));
}

__device__ __forceinline__ void stg256(float* __restrict__ p, const float r[8]) {
    asm volatile("st.global.v8.f32 [%0], {%1,%2,%3,%4,%5,%6,%7,%8};"
        :: "l"(p),
           "f"(r[0]), "f"(r[1]), "f"(r[2]), "f"(r[3]),
           "f"(r[4]), "f"(r[5]), "f"(r[6]), "f"(r[7])
        : "memory");
}

__global__ __launch_bounds__(WARPS_PER_BLOCK * 32)
void token_mixer_kernel(const float* __restrict__ pre,
                        const float* __restrict__ pos,
                        float* __restrict__ out) {
    const int warp_id = threadIdx.x >> 5;
    const int lane    = threadIdx.x & 31;
    const int row     = blockIdx.x * WARPS_PER_BLOCK + warp_id;  // exact: 2048*32 == ROWS_TOTAL

    const size_t base = (size_t)row * FLOATS_PER_ROW + lane * 8;
    const float* __restrict__ p = pre + base;
    const float* __restrict__ q = pos + base;

    // Front-batch: 4 x 256-bit loads (2 per input). Warp covers 1KB per op.
    float a0[8], a1[8], b0[8], b1[8];
    ldg256(p,       a0);
    ldg256(q,       b0);
    ldg256(p + 256, a1);
    ldg256(q + 256, b1);

    float dot = 0.f, sa = 0.f, sb = 0.f;
    #pragma unroll
    for (int i = 0; i < 8; i++) {
        dot += a0[i] * b0[i];
        sa  += a0[i] * a0[i];
        sb  += b0[i] * b0[i];
        dot += a1[i] * b1[i];
        sa  += a1[i] * a1[i];
        sb  += b1[i] * b1[i];
    }

    // Warp tree-reduce the three scalars (interleaved chains).
    #pragma unroll
    for (int off = 16; off > 0; off >>= 1) {
        dot += __shfl_xor_sync(0xffffffffu, dot, off);
        sa  += __shfl_xor_sync(0xffffffffu, sa,  off);
        sb  += __shfl_xor_sync(0xffffffffu, sb,  off);
    }

    // 1/max(sqrt(s), 1e-12) == min(rsqrt(s), 1e12): two MUFU.RSQ, no div.
    const float ra = fminf(rsqrtf(sa), 1e12f);
    const float rb = fminf(rsqrtf(sb), 1e12f);
    const float d  = dot * ra * rb;
    // 1 - sigmoid(d) = 1 / (1 + exp(d))
    const float w  = 1.0f / (1.0f + __expf(d));

    #pragma unroll
    for (int i = 0; i < 8; i++) { b0[i] *= w; b1[i] *= w; }

    float* __restrict__ o = out + base;
    stg256(o,       b0);
    stg256(o + 256, b1);
}

extern "C" void kernel_launch(void* const* d_in, const int* in_sizes, int n_in,
                              void* d_out, int out_size) {
    const float* pre = (const float*)d_in[0];
    const float* pos = (const float*)d_in[1];
    float* out = (float*)d_out;
    const int blocks = ROWS_TOTAL / WARPS_PER_BLOCK;  // 2048
    token_mixer_kernel<<<blocks, WARPS_PER_BLOCK * 32>>>(pre, pos, out);
}